// round 1
// baseline (speedup 1.0000x reference)
#include <cuda_runtime.h>
#include <math.h>

#define HID 300
#define NNODES 80000
#define NEDGES 160000
#define HALF 80000
#define NGRAPHS 1600
#define NODE_DIM 133
#define EDGE_DIM 14

// ---------------- scratch ----------------
__device__ float g_h  [NEDGES * HID];
__device__ float g_h2 [NEDGES * HID];
__device__ float g_inc[NNODES * HID];
__device__ float g_shared[NNODES * HID];
__device__ float g_mu [NNODES * HID];
__device__ float g_lv [NNODES * HID];
__device__ float g_mug[NGRAPHS * HID];
__device__ float g_lvg[NGRAPHS * HID];
__device__ float g_cnt[NGRAPHS];

// edge index helpers: src = cat(src_half, dst_half), dst = cat(dst_half, src_half)
__device__ __forceinline__ int e_src(int e, const int* sh, const int* dh) {
    return e < HALF ? sh[e] : dh[e - HALF];
}
__device__ __forceinline__ int e_dst(int e, const int* sh, const int* dh) {
    return e < HALF ? dh[e] : sh[e - HALF];
}
__device__ __forceinline__ int e_rev(int e) {
    return e < HALF ? e + HALF : e - HALF;
}

// ---------------- generic tiled SGEMM with fused gather A ----------------
// C[M, 300] = A[M, K] @ W[K, 300] (+ bias, + optional residual/relu)
// MODE 0 (edge lin):  A[e][k] = k<IN ? A1[src(e)*IN + k] : A2[e*EDGE_DIM + k-IN]
// MODE 1 (mp step):   A[e][k] = A1[src(e)*HID + k] - A2[rev(e)*HID + k]
//                     epilogue: C = relu(A2[e][c] + acc + bias)
// MODE 2 (atom upd):  A[n][k] = k<IN ? A1[n*IN + k] : A2[n*HID + k-IN]
template <int MODE>
__global__ void gemm_kernel(const float* __restrict__ A1,
                            const float* __restrict__ A2,
                            const float* __restrict__ W,
                            const float* __restrict__ bias,
                            const int* __restrict__ sh,
                            const int* __restrict__ dh,
                            float* __restrict__ C,
                            int M, int K, int IN, int do_relu) {
    __shared__ float As[64][17];
    __shared__ float Bs[16][64];

    const int bm = blockIdx.x * 64;
    const int bn = blockIdx.y * 64;
    const int tid = threadIdx.x;          // 256 threads
    const int tx = tid & 15;
    const int ty = tid >> 4;

    float acc[4][4];
#pragma unroll
    for (int i = 0; i < 4; i++)
#pragma unroll
        for (int j = 0; j < 4; j++) acc[i][j] = 0.f;

    for (int k0 = 0; k0 < K; k0 += 16) {
        // ---- load A tile: 64 rows x 16 k, each thread loads 4 contiguous k of one row
        {
            const int idx = tid * 4;
            const int r = idx >> 4;
            const int kk = idx & 15;
            const int row = bm + r;
            if (row < M) {
                if (MODE == 0) {
                    const int s = e_src(row, sh, dh);
#pragma unroll
                    for (int j = 0; j < 4; j++) {
                        const int k = k0 + kk + j;
                        float v = 0.f;
                        if (k < K) v = (k < IN) ? A1[s * IN + k]
                                                : A2[row * EDGE_DIM + (k - IN)];
                        As[r][kk + j] = v;
                    }
                } else if (MODE == 1) {
                    const int s = e_src(row, sh, dh);
                    const int rv = e_rev(row);
#pragma unroll
                    for (int j = 0; j < 4; j++) {
                        const int k = k0 + kk + j;
                        float v = 0.f;
                        if (k < K) v = A1[s * HID + k] - A2[rv * HID + k];
                        As[r][kk + j] = v;
                    }
                } else {
#pragma unroll
                    for (int j = 0; j < 4; j++) {
                        const int k = k0 + kk + j;
                        float v = 0.f;
                        if (k < K) v = (k < IN) ? A1[row * IN + k]
                                                : A2[row * HID + (k - IN)];
                        As[r][kk + j] = v;
                    }
                }
            } else {
#pragma unroll
                for (int j = 0; j < 4; j++) As[r][kk + j] = 0.f;
            }
        }
        // ---- load B tile: 16 k x 64 cols
        {
            const int idx = tid * 4;
            const int kr = idx >> 6;
            const int c = idx & 63;
            const int gk = k0 + kr;
#pragma unroll
            for (int j = 0; j < 4; j++) {
                const int gc = bn + c + j;
                Bs[kr][c + j] = (gk < K && gc < HID) ? W[gk * HID + gc] : 0.f;
            }
        }
        __syncthreads();

#pragma unroll
        for (int kk = 0; kk < 16; kk++) {
            float a[4];
#pragma unroll
            for (int i = 0; i < 4; i++) a[i] = As[ty * 4 + i][kk];
            const float4 bv = *reinterpret_cast<const float4*>(&Bs[kk][tx * 4]);
            const float b[4] = {bv.x, bv.y, bv.z, bv.w};
#pragma unroll
            for (int i = 0; i < 4; i++)
#pragma unroll
                for (int j = 0; j < 4; j++) acc[i][j] += a[i] * b[j];
        }
        __syncthreads();
    }

    // ---- epilogue
#pragma unroll
    for (int i = 0; i < 4; i++) {
        const int row = bm + ty * 4 + i;
        if (row >= M) continue;
#pragma unroll
        for (int j = 0; j < 4; j++) {
            const int c = bn + tx * 4 + j;
            if (c >= HID) continue;
            float v = acc[i][j] + bias[c];
            if (MODE == 1) {
                v += A2[row * HID + c];     // residual h
                v = fmaxf(v, 0.f);
            } else if (do_relu) {
                v = fmaxf(v, 0.f);
            }
            C[row * HID + c] = v;
        }
    }
}

// ---------------- segment sum over edges: inc[dst(e)] += h[e] ----------------
__global__ void segsum_kernel(const float* __restrict__ h,
                              float* __restrict__ inc,
                              const int* __restrict__ sh,
                              const int* __restrict__ dh) {
    const int idx = blockIdx.x * blockDim.x + threadIdx.x;
    const int e = idx / 75;         // 300/4 float4 chunks
    const int ch = idx % 75;
    if (e >= NEDGES) return;
    const int d = e_dst(e, sh, dh);
    const float4 v = *reinterpret_cast<const float4*>(&h[e * HID + ch * 4]);
    float* base = &inc[d * HID + ch * 4];
    atomicAdd(base + 0, v.x);
    atomicAdd(base + 1, v.y);
    atomicAdd(base + 2, v.z);
    atomicAdd(base + 3, v.w);
}

__global__ void zero_kernel(float* __restrict__ p, long n) {
    long i = (long)blockIdx.x * blockDim.x + threadIdx.x;
    if (i < n) p[i] = 0.f;
}

// ---------------- graph pooling ----------------
__global__ void pool_cnt_kernel(const int* __restrict__ batch) {
    const int n = blockIdx.x * blockDim.x + threadIdx.x;
    if (n >= NNODES) return;
    atomicAdd(&g_cnt[batch[n]], 1.f);
}

__global__ void pool_acc_kernel(const float* __restrict__ mu,
                                const float* __restrict__ lv,
                                const float* __restrict__ W_atoms,
                                const int* __restrict__ batch) {
    const int idx = blockIdx.x * blockDim.x + threadIdx.x;
    const int n = idx / 75;
    const int ch = idx % 75;
    if (n >= NNODES) return;
    const float w = W_atoms[n];
    const int b = batch[n];
    const float4 m = *reinterpret_cast<const float4*>(&mu[n * HID + ch * 4]);
    const float4 l = *reinterpret_cast<const float4*>(&lv[n * HID + ch * 4]);
    float* mb = &g_mug[b * HID + ch * 4];
    float* lb = &g_lvg[b * HID + ch * 4];
    atomicAdd(mb + 0, m.x * w); atomicAdd(mb + 1, m.y * w);
    atomicAdd(mb + 2, m.z * w); atomicAdd(mb + 3, m.w * w);
    atomicAdd(lb + 0, l.x * w); atomicAdd(lb + 1, l.y * w);
    atomicAdd(lb + 2, l.z * w); atomicAdd(lb + 3, l.w * w);
}

__global__ void finalize_kernel(const float* __restrict__ eps,
                                float* __restrict__ out) {
    const int idx = blockIdx.x * blockDim.x + threadIdx.x;
    if (idx >= NGRAPHS * HID) return;
    const int g = idx / HID;
    const float c = fmaxf(g_cnt[g], 1.f);
    const float mug = g_mug[idx] / c;
    const float lvg = g_lvg[idx] / c;
    out[idx] = mug + expf(0.5f * lvg) * eps[idx];
}

// ---------------- host side ----------------
static float* sym_addr(const void* s) {
    void* p = nullptr;
    cudaGetSymbolAddress(&p, s);
    return (float*)p;
}

static void launch_zero(float* p, long n) {
    int threads = 256;
    long blocks = (n + threads - 1) / threads;
    zero_kernel<<<(unsigned)blocks, threads>>>(p, n);
}

extern "C" void kernel_launch(void* const* d_in, const int* in_sizes, int n_in,
                              void* d_out, int out_size) {
    const float* x         = (const float*)d_in[0];
    const float* edge_attr = (const float*)d_in[1];
    const float* W_atoms   = (const float*)d_in[2];
    const float* eps       = (const float*)d_in[3];
    const int*   src_half  = (const int*)d_in[4];
    const int*   dst_half  = (const int*)d_in[5];
    const int*   batch     = (const int*)d_in[6];
    const float* t_lin_w = (const float*)d_in[7];
    const float* t_lin_b = (const float*)d_in[8];
    const float* t_mp_w  = (const float*)d_in[9];
    const float* t_mp_b  = (const float*)d_in[10];
    const float* t_au_w  = (const float*)d_in[11];
    const float* t_au_b  = (const float*)d_in[12];
    const float* mu_lin_w = (const float*)d_in[13];
    const float* mu_lin_b = (const float*)d_in[14];
    const float* mu_mp_w  = (const float*)d_in[15];
    const float* mu_mp_b  = (const float*)d_in[16];
    const float* mu_au_w  = (const float*)d_in[17];
    const float* mu_au_b  = (const float*)d_in[18];
    const float* lv_lin_w = (const float*)d_in[19];
    const float* lv_lin_b = (const float*)d_in[20];
    const float* lv_mp_w  = (const float*)d_in[21];
    const float* lv_mp_b  = (const float*)d_in[22];
    const float* lv_au_w  = (const float*)d_in[23];
    const float* lv_au_b  = (const float*)d_in[24];

    float* h      = sym_addr(g_h);
    float* h2     = sym_addr(g_h2);
    float* inc    = sym_addr(g_inc);
    float* shared = sym_addr(g_shared);
    float* mu     = sym_addr(g_mu);
    float* lv     = sym_addr(g_lv);
    float* mug    = sym_addr(g_mug);
    float* lvg    = sym_addr(g_lvg);
    float* cnt    = sym_addr(g_cnt);

    const int GT = 256;
    const int seg_blocks = (NEDGES * 75 + GT - 1) / GT;

    auto conv = [&](const float* node_in, int IN,
                    const float* lin_w, const float* lin_b,
                    const float* mp_w, const float* mp_b,
                    const float* au_w, const float* au_b,
                    float* outp, int out_relu) {
        // edge linear: h = relu(cat(node_in[src], edge_attr) @ lin_w + b)
        {
            dim3 grid((NEDGES + 63) / 64, (HID + 63) / 64);
            gemm_kernel<0><<<grid, 256>>>(node_in, edge_attr, lin_w, lin_b,
                                          src_half, dst_half, h,
                                          NEDGES, IN + EDGE_DIM, IN, 1);
        }
        float* hc = h;
        float* hn = h2;
        for (int i = 0; i < 3; i++) {
            launch_zero(inc, (long)NNODES * HID);
            segsum_kernel<<<seg_blocks, GT>>>(hc, inc, src_half, dst_half);
            dim3 grid((NEDGES + 63) / 64, (HID + 63) / 64);
            gemm_kernel<1><<<grid, 256>>>(inc, hc,
                                          mp_w + (long)i * HID * HID,
                                          mp_b + i * HID,
                                          src_half, dst_half, hn,
                                          NEDGES, HID, 0, 1);
            float* t = hc; hc = hn; hn = t;
        }
        // sum_inc for atom update
        launch_zero(inc, (long)NNODES * HID);
        segsum_kernel<<<seg_blocks, GT>>>(hc, inc, src_half, dst_half);
        {
            dim3 grid((NNODES + 63) / 64, (HID + 63) / 64);
            gemm_kernel<2><<<grid, 256>>>(node_in, inc, au_w, au_b,
                                          src_half, dst_half, outp,
                                          NNODES, IN + HID, IN, out_relu);
        }
    };

    conv(x, NODE_DIM, t_lin_w, t_lin_b, t_mp_w, t_mp_b, t_au_w, t_au_b, shared, 1);
    conv(shared, HID, mu_lin_w, mu_lin_b, mu_mp_w, mu_mp_b, mu_au_w, mu_au_b, mu, 0);
    conv(shared, HID, lv_lin_w, lv_lin_b, lv_mp_w, lv_mp_b, lv_au_w, lv_au_b, lv, 0);

    // pooling + reparameterization
    launch_zero(mug, (long)NGRAPHS * HID);
    launch_zero(lvg, (long)NGRAPHS * HID);
    launch_zero(cnt, NGRAPHS);
    pool_cnt_kernel<<<(NNODES + GT - 1) / GT, GT>>>(batch);
    pool_acc_kernel<<<(NNODES * 75 + GT - 1) / GT, GT>>>(mu, lv, W_atoms, batch);
    finalize_kernel<<<(NGRAPHS * HID + GT - 1) / GT, GT>>>(eps, (float*)d_out);
}